// round 15
// baseline (speedup 1.0000x reference)
#include <cuda_runtime.h>
#include <cuda_bf16.h>

// Problem constants
#define BATCH   32
#define NATOMS  1024
#define PAD     1028       // plane stride: 1028 mod 32 = 4 -> planes on distinct banks
#define ITILE   4          // output rows per block (best-measured config)
#define THREADS 256

// Minimum-image wrap without the divide, bit-exact vs the reference's
// rintf(__fdiv_rn(d, L)) * L for |d| < L:
// rn(d/L) > 0.5 <=> d > L/2 for representable d; tie at d == L/2 -> rint = 0.
__device__ __forceinline__ float wrapmi(float d, float L, float hl)
{
    float r = d;
    if (d >  hl) r = d - L;
    if (d < -hl) r = d + L;
    return r;
}

// R14 delta (single change vs the 4x-reproduced best): grid axes swapped so
// consecutive CTAs map to consecutive FRAMES (12.6 MB apart in the output)
// instead of adjacent 48 KB row-groups. Wave-1's ~1000 resident CTAs now
// spread their write streams across the full 403 MB address range ->
// maximal distribution over L2 slices and DRAM banks/channels. Everything
// else identical: rotation math, exact-4 wraps per 16B, coalesced STG.128
// (warp = contiguous 512B, full lines), __stcs, free regalloc.
//
// Converged context: DRAM write controller binds at ~6.87 TB/s production
// (~86% of spec). Neutral-or-worse: TMA bulk, LDS.128, issue 87->49%,
// .cs/.wt, STG.256, ITILE=8, reg-capped 90% occ. Best = 58.6-58.9us ncu.
__global__ __launch_bounds__(THREADS)
void rij_min_image_kernel(const float* __restrict__ pos,
                          const float* __restrict__ cell,
                          float* __restrict__ out)
{
    __shared__ float sp[3 * PAD];      // SoA planes: x @0, y @PAD, z @2*PAD

    const int b  = blockIdx.x;                 // frame (fast axis -> spread)
    const int i0 = blockIdx.y * ITILE;         // row group

    // Cooperative SoA fill, vectorized global reads (L2-resident after wave 1).
    const float4* pb4 = (const float4*)(pos + (size_t)b * NATOMS * 3);
    #pragma unroll
    for (int v = threadIdx.x; v < (NATOMS * 3) / 4; v += THREADS) {
        const float4 w = pb4[v];
        const int f = 4 * v;
        sp[((f + 0) % 3) * PAD + (f + 0) / 3] = w.x;
        sp[((f + 1) % 3) * PAD + (f + 1) / 3] = w.y;
        sp[((f + 2) % 3) * PAD + (f + 2) / 3] = w.z;
        sp[((f + 3) % 3) * PAD + (f + 3) / 3] = w.w;
    }

    // Box lengths from the cell diagonal; L/2 exact in binary FP.
    const float Lx = cell[(size_t)b * 9 + 0];
    const float Ly = cell[(size_t)b * 9 + 4];
    const float Lz = cell[(size_t)b * 9 + 8];
    const float Hx = 0.5f * Lx, Hy = 0.5f * Ly, Hz = 0.5f * Lz;

    __syncthreads();

    float* orow = out + ((size_t)b * NATOMS + i0) * NATOMS * 3;

    #pragma unroll
    for (int s = 0; s < 3; ++s) {
        const int q  = s * THREADS + threadIdx.x;   // float4 index in row
        const int f0 = 4 * q;
        const int ja = f0 / 3;                      // first atom (<= 1022)
        const int r  = f0 - 3 * ja;                 // 0, 1, or 2

        // Rotated axes: e0 = r, e1 = (r+1) mod 3, e2 = (r+2) mod 3.
        const int e0 = r;
        const int e1 = (r == 2) ? 0 : r + 1;
        const int e2 = (r == 0) ? 2 : r - 1;

        // Atoms per component k: ja for k < 3-r, else ja+1.
        const int a1 = (r >= 2) ? ja + 1 : ja;      // k=1
        const int a2 = (r >= 1) ? ja + 1 : ja;      // k=2

        // Column-atom coordinates (4 scalar LDS per s, reused over ITILE rows).
        const float pj0 = sp[e0 * PAD + ja];
        const float pj1 = sp[e1 * PAD + a1];
        const float pj2 = sp[e2 * PAD + a2];
        const float pj3 = sp[e0 * PAD + ja + 1];

        // Per-component box length / half-box, resolved once per s.
        const float L0 = (r == 0) ? Lx : ((r == 1) ? Ly : Lz);
        const float L1 = (r == 0) ? Ly : ((r == 1) ? Lz : Lx);
        const float L2 = (r == 0) ? Lz : ((r == 1) ? Lx : Ly);
        const float H0 = (r == 0) ? Hx : ((r == 1) ? Hy : Hz);
        const float H1 = (r == 0) ? Hy : ((r == 1) ? Hz : Hx);
        const float H2 = (r == 0) ? Hz : ((r == 1) ? Hx : Hy);

        // Row-atom planes, rotated: immediate-offset LDS inside the loop.
        const float* pe0 = sp + e0 * PAD + i0;
        const float* pe1 = sp + e1 * PAD + i0;
        const float* pe2 = sp + e2 * PAD + i0;

        float4* dst = (float4*)orow + q;            // + ii*768 via immediates

        #pragma unroll
        for (int ii = 0; ii < ITILE; ++ii) {
            const float p0 = pe0[ii];
            const float p1 = pe1[ii];
            const float p2 = pe2[ii];

            float4 v;
            v.x = wrapmi(p0 - pj0, L0, H0);
            v.y = wrapmi(p1 - pj1, L1, H1);
            v.z = wrapmi(p2 - pj2, L2, H2);
            v.w = wrapmi(p0 - pj3, L0, H0);

            __stcs(dst + (size_t)ii * (NATOMS * 3 / 4), v);
        }
    }
}

extern "C" void kernel_launch(void* const* d_in, const int* in_sizes, int n_in,
                              void* d_out, int out_size)
{
    const float* positions = (const float*)d_in[0];  // (32, 1024, 3)
    const float* cell      = (const float*)d_in[1];  // (32, 3, 3)
    float* out             = (float*)d_out;          // (32, 1024, 1024, 3)

    dim3 grid(BATCH, NATOMS / ITILE);   // (32, 256) = 8192 blocks, frame-fast
    rij_min_image_kernel<<<grid, THREADS>>>(positions, cell, out);
}

// round 16
// speedup vs baseline: 1.0345x; 1.0345x over previous
#include <cuda_runtime.h>
#include <cuda_bf16.h>

// Problem constants
#define BATCH   32
#define NATOMS  1024
#define PAD     1028       // plane stride: 1028 mod 32 = 4 -> planes on distinct banks
#define ITILE   4          // output rows per block (best-measured config)
#define THREADS 256

// Minimum-image wrap without the divide, bit-exact vs the reference's
// rintf(__fdiv_rn(d, L)) * L for |d| < L:
// rn(d/L) > 0.5 <=> d > L/2 for representable d; tie at d == L/2 -> rint = 0.
__device__ __forceinline__ float wrapmi(float d, float L, float hl)
{
    float r = d;
    if (d >  hl) r = d - L;
    if (d < -hl) r = d + L;
    return r;
}

// FINAL (converged after 15 rounds; this exact config reproduced
// 58.6-58.9us ncu / 59.4us bench four times — R8, R10, R12, R14).
//
// Each block handles one frame b and ITILE consecutive i-rows.
// Row = 3072 floats = 768 float4s. Thread t stores float4 q = s*256 + t for
// s = 0..2 -> every warp STG.128 covers a contiguous 512B span (coalesced,
// full 128B lines, pure write stream, no RMW reads).
// Component c of float4 q maps to atom (4q+c)/3, axis (4q+c)%3; with
// r = 4q mod 3 the axes are the rotation (e0,e1,e2,e0) of (x,y,z) and the
// atoms are ja (first 3-r components) then ja+1 — resolved once per s, so
// the inner loop computes exactly 4 wraps per 16B stored.
//
// Convergence evidence: binding constraint is the DRAM write controller at
// ~6.87 TB/s production (~86% of 8 TB/s spec). Measured neutral-or-worse:
// TMA bulk stores, LDS.128 reads, issue reduction (87%->49%), .cs vs .wt,
// STG.256 (v8.f32), ITILE=8, reg-capped 90% occ (spills, 66us), and
// frame-fast CTA interleaving (channel hash already uniformizes).
__global__ __launch_bounds__(THREADS)
void rij_min_image_kernel(const float* __restrict__ pos,
                          const float* __restrict__ cell,
                          float* __restrict__ out)
{
    __shared__ float sp[3 * PAD];      // SoA planes: x @0, y @PAD, z @2*PAD

    const int b  = blockIdx.y;
    const int i0 = blockIdx.x * ITILE;

    // Cooperative SoA fill, vectorized global reads (L2-resident after wave 1).
    const float4* pb4 = (const float4*)(pos + (size_t)b * NATOMS * 3);
    #pragma unroll
    for (int v = threadIdx.x; v < (NATOMS * 3) / 4; v += THREADS) {
        const float4 w = pb4[v];
        const int f = 4 * v;
        sp[((f + 0) % 3) * PAD + (f + 0) / 3] = w.x;
        sp[((f + 1) % 3) * PAD + (f + 1) / 3] = w.y;
        sp[((f + 2) % 3) * PAD + (f + 2) / 3] = w.z;
        sp[((f + 3) % 3) * PAD + (f + 3) / 3] = w.w;
    }

    // Box lengths from the cell diagonal; L/2 exact in binary FP.
    const float Lx = cell[(size_t)b * 9 + 0];
    const float Ly = cell[(size_t)b * 9 + 4];
    const float Lz = cell[(size_t)b * 9 + 8];
    const float Hx = 0.5f * Lx, Hy = 0.5f * Ly, Hz = 0.5f * Lz;

    __syncthreads();

    float* orow = out + ((size_t)b * NATOMS + i0) * NATOMS * 3;

    #pragma unroll
    for (int s = 0; s < 3; ++s) {
        const int q  = s * THREADS + threadIdx.x;   // float4 index in row
        const int f0 = 4 * q;
        const int ja = f0 / 3;                      // first atom (<= 1022)
        const int r  = f0 - 3 * ja;                 // 0, 1, or 2

        // Rotated axes: e0 = r, e1 = (r+1) mod 3, e2 = (r+2) mod 3.
        const int e0 = r;
        const int e1 = (r == 2) ? 0 : r + 1;
        const int e2 = (r == 0) ? 2 : r - 1;

        // Atoms per component k: ja for k < 3-r, else ja+1.
        const int a1 = (r >= 2) ? ja + 1 : ja;      // k=1
        const int a2 = (r >= 1) ? ja + 1 : ja;      // k=2

        // Column-atom coordinates (4 scalar LDS per s, reused over ITILE rows).
        const float pj0 = sp[e0 * PAD + ja];
        const float pj1 = sp[e1 * PAD + a1];
        const float pj2 = sp[e2 * PAD + a2];
        const float pj3 = sp[e0 * PAD + ja + 1];

        // Per-component box length / half-box, resolved once per s.
        const float L0 = (r == 0) ? Lx : ((r == 1) ? Ly : Lz);
        const float L1 = (r == 0) ? Ly : ((r == 1) ? Lz : Lx);
        const float L2 = (r == 0) ? Lz : ((r == 1) ? Lx : Ly);
        const float H0 = (r == 0) ? Hx : ((r == 1) ? Hy : Hz);
        const float H1 = (r == 0) ? Hy : ((r == 1) ? Hz : Hx);
        const float H2 = (r == 0) ? Hz : ((r == 1) ? Hx : Hy);

        // Row-atom planes, rotated: immediate-offset LDS inside the loop.
        const float* pe0 = sp + e0 * PAD + i0;
        const float* pe1 = sp + e1 * PAD + i0;
        const float* pe2 = sp + e2 * PAD + i0;

        float4* dst = (float4*)orow + q;            // + ii*768 via immediates

        #pragma unroll
        for (int ii = 0; ii < ITILE; ++ii) {
            const float p0 = pe0[ii];
            const float p1 = pe1[ii];
            const float p2 = pe2[ii];

            float4 v;
            v.x = wrapmi(p0 - pj0, L0, H0);
            v.y = wrapmi(p1 - pj1, L1, H1);
            v.z = wrapmi(p2 - pj2, L2, H2);
            v.w = wrapmi(p0 - pj3, L0, H0);

            __stcs(dst + (size_t)ii * (NATOMS * 3 / 4), v);
        }
    }
}

extern "C" void kernel_launch(void* const* d_in, const int* in_sizes, int n_in,
                              void* d_out, int out_size)
{
    const float* positions = (const float*)d_in[0];  // (32, 1024, 3)
    const float* cell      = (const float*)d_in[1];  // (32, 3, 3)
    float* out             = (float*)d_out;          // (32, 1024, 1024, 3)

    dim3 grid(NATOMS / ITILE, BATCH);   // (256, 32) = 8192 blocks
    rij_min_image_kernel<<<grid, THREADS>>>(positions, cell, out);
}